// round 1
// baseline (speedup 1.0000x reference)
#include <cuda_runtime.h>

#define NN 10000
#define NE 640000
// IN=128, HID=256, OUT=128

// ---------------- scratch (no allocations allowed) ----------------
__device__ int   g_cnt[NN];        // degree counts, then reused as fill cursor
__device__ int   g_row[NN + 1];    // CSR row offsets
__device__ int   g_col[NE];        // CSR column (src node per edge, grouped by dst)
__device__ float g_agg[NN * 128];  // aggregation output (layer1 and layer2 reuse)
__device__ float g_h[NN * 256];    // hidden activations
__device__ float g_t[NN * 128];    // h @ w_neigh2 (pre-aggregation, layer2)

// ---------------- CSR build ----------------
__global__ void k_zero() {
    int i = blockIdx.x * blockDim.x + threadIdx.x;
    if (i < NN) g_cnt[i] = 0;
}

__global__ void k_count(const int* __restrict__ dst) {
    int e = blockIdx.x * blockDim.x + threadIdx.x;
    if (e < NE) atomicAdd(&g_cnt[dst[e]], 1);
}

// single-block exclusive scan over 10000 counts; also primes cursor (g_cnt)
__global__ void k_scan() {
    __shared__ int part[1024];
    const int CH = 10;  // 1024*10 >= 10000
    int t = threadIdx.x;
    int base = t * CH;
    int loc[CH];
    int s = 0;
#pragma unroll
    for (int i = 0; i < CH; i++) {
        int idx = base + i;
        int v = (idx < NN) ? g_cnt[idx] : 0;
        loc[i] = s;
        s += v;
    }
    part[t] = s;
    __syncthreads();
    for (int off = 1; off < 1024; off <<= 1) {
        int v = (t >= off) ? part[t - off] : 0;
        __syncthreads();
        part[t] += v;
        __syncthreads();
    }
    int offs = (t > 0) ? part[t - 1] : 0;
#pragma unroll
    for (int i = 0; i < CH; i++) {
        int idx = base + i;
        if (idx < NN) {
            int r = offs + loc[i];
            g_row[idx] = r;
            g_cnt[idx] = r;  // cursor for fill
        }
    }
    if (t == 0) g_row[NN] = NE;
}

__global__ void k_fill(const int* __restrict__ src, const int* __restrict__ dst) {
    int e = blockIdx.x * blockDim.x + threadIdx.x;
    if (e < NE) {
        int p = atomicAdd(&g_cnt[dst[e]], 1);
        g_col[p] = src[e];
    }
}

// ---------------- mean aggregation: warp per node, 128 floats = 32 lanes x float4 ----------------
__global__ void k_agg(const float* __restrict__ feat, float* __restrict__ out) {
    int warp = (blockIdx.x * blockDim.x + threadIdx.x) >> 5;
    int lane = threadIdx.x & 31;
    if (warp >= NN) return;
    int beg = g_row[warp];
    int end = g_row[warp + 1];
    const float4* f = (const float4*)feat;

    float4 a0 = make_float4(0.f, 0.f, 0.f, 0.f);
    float4 a1 = a0, a2 = a0, a3 = a0;
    int e = beg;
    for (; e + 4 <= end; e += 4) {
        int s0 = g_col[e + 0];
        int s1 = g_col[e + 1];
        int s2 = g_col[e + 2];
        int s3 = g_col[e + 3];
        float4 v0 = __ldg(&f[s0 * 32 + lane]);
        float4 v1 = __ldg(&f[s1 * 32 + lane]);
        float4 v2 = __ldg(&f[s2 * 32 + lane]);
        float4 v3 = __ldg(&f[s3 * 32 + lane]);
        a0.x += v0.x; a0.y += v0.y; a0.z += v0.z; a0.w += v0.w;
        a1.x += v1.x; a1.y += v1.y; a1.z += v1.z; a1.w += v1.w;
        a2.x += v2.x; a2.y += v2.y; a2.z += v2.z; a2.w += v2.w;
        a3.x += v3.x; a3.y += v3.y; a3.z += v3.z; a3.w += v3.w;
    }
    for (; e < end; e++) {
        int s = g_col[e];
        float4 v = __ldg(&f[s * 32 + lane]);
        a0.x += v.x; a0.y += v.y; a0.z += v.z; a0.w += v.w;
    }
    a0.x += a1.x + a2.x + a3.x;
    a0.y += a1.y + a2.y + a3.y;
    a0.z += a1.z + a2.z + a3.z;
    a0.w += a1.w + a2.w + a3.w;

    float inv = 1.0f / fmaxf((float)(end - beg), 1.0f);
    a0.x *= inv; a0.y *= inv; a0.z *= inv; a0.w *= inv;
    ((float4*)out)[warp * 32 + lane] = a0;
}

// ---------------- fused SGEMM: C = A1@B1 (+A2@B2) (+add) (+bias), optional ReLU ----------------
// BM=BN=64, BK=16, 256 threads, 4x4 micro-tile per thread
template <int K, bool DUAL, bool ADDEND, bool BIAS, bool RELU>
__global__ __launch_bounds__(256)
void k_gemm(const float* __restrict__ A1, const float* __restrict__ B1,
            const float* __restrict__ A2, const float* __restrict__ B2,
            const float* __restrict__ add, const float* __restrict__ bias,
            float* __restrict__ C, int M, int N) {
    __shared__ float As1[16][65];
    __shared__ float Bs1[16][65];
    __shared__ float As2[DUAL ? 16 : 1][65];
    __shared__ float Bs2[DUAL ? 16 : 1][65];

    int tid = threadIdx.x;
    int tx = tid & 15;   // 0..15 -> 4 cols each
    int ty = tid >> 4;   // 0..15 -> 4 rows each
    int m0 = blockIdx.y * 64;
    int n0 = blockIdx.x * 64;

    float acc[4][4] = {};

    for (int k0 = 0; k0 < K; k0 += 16) {
#pragma unroll
        for (int c = 0; c < 4; c++) {
            int idx = tid + c * 256;  // 0..1023
            int am = idx >> 4, ak = idx & 15;
            int gm = m0 + am;
            As1[ak][am] = (gm < M) ? A1[gm * K + k0 + ak] : 0.f;
            if (DUAL) As2[ak][am] = (gm < M) ? A2[gm * K + k0 + ak] : 0.f;
            int bn = idx & 63, bk = idx >> 6;
            Bs1[bk][bn] = B1[(k0 + bk) * N + n0 + bn];
            if (DUAL) Bs2[bk][bn] = B2[(k0 + bk) * N + n0 + bn];
        }
        __syncthreads();
#pragma unroll
        for (int k = 0; k < 16; k++) {
            float a1[4], b1[4];
            float a2[4], b2[4];
#pragma unroll
            for (int i = 0; i < 4; i++) {
                a1[i] = As1[k][ty * 4 + i];
                b1[i] = Bs1[k][tx * 4 + i];
            }
            if (DUAL) {
#pragma unroll
                for (int i = 0; i < 4; i++) {
                    a2[i] = As2[k][ty * 4 + i];
                    b2[i] = Bs2[k][tx * 4 + i];
                }
            }
#pragma unroll
            for (int i = 0; i < 4; i++)
#pragma unroll
                for (int j = 0; j < 4; j++) {
                    acc[i][j] += a1[i] * b1[j];
                    if (DUAL) acc[i][j] += a2[i] * b2[j];
                }
        }
        __syncthreads();
    }

#pragma unroll
    for (int i = 0; i < 4; i++) {
        int m = m0 + ty * 4 + i;
        if (m >= M) continue;
#pragma unroll
        for (int j = 0; j < 4; j++) {
            int n = n0 + tx * 4 + j;
            float v = acc[i][j];
            if (BIAS) v += bias[n];
            if (ADDEND) v += add[m * N + n];
            if (RELU) v = fmaxf(v, 0.f);
            C[m * N + n] = v;
        }
    }
}

// ---------------- launch ----------------
extern "C" void kernel_launch(void* const* d_in, const int* in_sizes, int n_in,
                              void* d_out, int out_size) {
    const float* x   = (const float*)d_in[0];
    const float* ws1 = (const float*)d_in[1];
    const float* wn1 = (const float*)d_in[2];
    const float* b1  = (const float*)d_in[3];
    const float* ws2 = (const float*)d_in[4];
    const float* wn2 = (const float*)d_in[5];
    const float* b2  = (const float*)d_in[6];
    const int*   src = (const int*)d_in[7];
    const int*   dst = (const int*)d_in[8];
    float* out = (float*)d_out;

    float *agg, *h, *t;
    cudaGetSymbolAddress((void**)&agg, g_agg);
    cudaGetSymbolAddress((void**)&h, g_h);
    cudaGetSymbolAddress((void**)&t, g_t);

    // CSR build (per call; graph-capturable, no allocs)
    k_zero<<<(NN + 255) / 256, 256>>>();
    k_count<<<(NE + 255) / 256, 256>>>(dst);
    k_scan<<<1, 1024>>>();
    k_fill<<<(NE + 255) / 256, 256>>>(src, dst);

    // layer 1: agg1 = mean_agg(x); h = relu(x@ws1 + agg1@wn1 + b1)
    int agg_blocks = (NN * 32 + 255) / 256;
    k_agg<<<agg_blocks, 256>>>(x, agg);
    dim3 g1(256 / 64, (NN + 63) / 64);
    k_gemm<128, true, false, true, true><<<g1, 256>>>(x, ws1, agg, wn1, nullptr, b1, h, NN, 256);

    // layer 2 (reordered): t = h@wn2; agg2 = mean_agg(t); out = h@ws2 + agg2 + b2
    dim3 g2(128 / 64, (NN + 63) / 64);
    k_gemm<256, false, false, false, false><<<g2, 256>>>(h, wn2, nullptr, nullptr, nullptr, nullptr, t, NN, 128);
    k_agg<<<agg_blocks, 256>>>(t, agg);
    k_gemm<256, false, true, true, false><<<g2, 256>>>(h, ws2, nullptr, nullptr, agg, b2, out, NN, 128);
}

// round 2
// speedup vs baseline: 1.1438x; 1.1438x over previous
#include <cuda_runtime.h>

#define NN 10000
#define NE 640000
// IN=128, HID=256, OUT=128

// ---------------- scratch (no allocations allowed) ----------------
__device__ int   g_cnt[NN];        // degree counts, then reused as fill cursor
__device__ int   g_row[NN + 1];    // CSR row offsets
__device__ int   g_col[NE];        // CSR column (src node per edge, grouped by dst)
__device__ float g_agg[NN * 128];  // aggregation output (layer1 and layer2 reuse)
__device__ float g_h[NN * 256];    // hidden activations
__device__ float g_t[NN * 128];    // h @ w_neigh2 (pre-aggregation, layer2)

// ---------------- f32x2 helpers ----------------
__device__ __forceinline__ unsigned long long bcast2(float a) {
    unsigned long long d;
    unsigned int u = __float_as_uint(a);
    asm("mov.b64 %0, {%1, %1};" : "=l"(d) : "r"(u));
    return d;
}
__device__ __forceinline__ unsigned long long ffma2(unsigned long long a,
                                                    unsigned long long b,
                                                    unsigned long long c) {
    unsigned long long d;
    asm("fma.rn.f32x2 %0, %1, %2, %3;" : "=l"(d) : "l"(a), "l"(b), "l"(c));
    return d;
}
__device__ __forceinline__ void unpack2(unsigned long long v, float& lo, float& hi) {
    unsigned int a, b;
    asm("mov.b64 {%0, %1}, %2;" : "=r"(a), "=r"(b) : "l"(v));
    lo = __uint_as_float(a);
    hi = __uint_as_float(b);
}

// ---------------- CSR build ----------------
__global__ void k_zero() {
    int i = blockIdx.x * blockDim.x + threadIdx.x;
    if (i < NN) g_cnt[i] = 0;
}

__global__ void k_count(const int* __restrict__ dst) {
    int e = blockIdx.x * blockDim.x + threadIdx.x;
    if (e < NE) atomicAdd(&g_cnt[dst[e]], 1);
}

// single-block exclusive scan over 10000 counts; also primes cursor (g_cnt)
__global__ void k_scan() {
    __shared__ int part[1024];
    const int CH = 10;  // 1024*10 >= 10000
    int t = threadIdx.x;
    int base = t * CH;
    int loc[CH];
    int s = 0;
#pragma unroll
    for (int i = 0; i < CH; i++) {
        int idx = base + i;
        int v = (idx < NN) ? g_cnt[idx] : 0;
        loc[i] = s;
        s += v;
    }
    part[t] = s;
    __syncthreads();
    for (int off = 1; off < 1024; off <<= 1) {
        int v = (t >= off) ? part[t - off] : 0;
        __syncthreads();
        part[t] += v;
        __syncthreads();
    }
    int offs = (t > 0) ? part[t - 1] : 0;
#pragma unroll
    for (int i = 0; i < CH; i++) {
        int idx = base + i;
        if (idx < NN) {
            int r = offs + loc[i];
            g_row[idx] = r;
            g_cnt[idx] = r;  // cursor for fill
        }
    }
    if (t == 0) g_row[NN] = NE;
}

__global__ void k_fill(const int* __restrict__ src, const int* __restrict__ dst) {
    int e = blockIdx.x * blockDim.x + threadIdx.x;
    if (e < NE) {
        int p = atomicAdd(&g_cnt[dst[e]], 1);
        g_col[p] = src[e];
    }
}

// ---------------- mean aggregation: warp per node, 128 floats = 32 lanes x float4 ----------------
__global__ void k_agg(const float* __restrict__ feat, float* __restrict__ out) {
    int warp = (blockIdx.x * blockDim.x + threadIdx.x) >> 5;
    int lane = threadIdx.x & 31;
    if (warp >= NN) return;
    int beg = g_row[warp];
    int end = g_row[warp + 1];
    const float4* f = (const float4*)feat;

    float4 a0 = make_float4(0.f, 0.f, 0.f, 0.f);
    float4 a1 = a0, a2 = a0, a3 = a0;
    int e = beg;
    for (; e + 4 <= end; e += 4) {
        int s0 = g_col[e + 0];
        int s1 = g_col[e + 1];
        int s2 = g_col[e + 2];
        int s3 = g_col[e + 3];
        float4 v0 = __ldg(&f[s0 * 32 + lane]);
        float4 v1 = __ldg(&f[s1 * 32 + lane]);
        float4 v2 = __ldg(&f[s2 * 32 + lane]);
        float4 v3 = __ldg(&f[s3 * 32 + lane]);
        a0.x += v0.x; a0.y += v0.y; a0.z += v0.z; a0.w += v0.w;
        a1.x += v1.x; a1.y += v1.y; a1.z += v1.z; a1.w += v1.w;
        a2.x += v2.x; a2.y += v2.y; a2.z += v2.z; a2.w += v2.w;
        a3.x += v3.x; a3.y += v3.y; a3.z += v3.z; a3.w += v3.w;
    }
    for (; e < end; e++) {
        int s = g_col[e];
        float4 v = __ldg(&f[s * 32 + lane]);
        a0.x += v.x; a0.y += v.y; a0.z += v.z; a0.w += v.w;
    }
    a0.x += a1.x + a2.x + a3.x;
    a0.y += a1.y + a2.y + a3.y;
    a0.z += a1.z + a2.z + a3.z;
    a0.w += a1.w + a2.w + a3.w;

    float inv = 1.0f / fmaxf((float)(end - beg), 1.0f);
    a0.x *= inv; a0.y *= inv; a0.z *= inv; a0.w *= inv;
    ((float4*)out)[warp * 32 + lane] = a0;
}

// ---------------- f32x2 SGEMM: C = concatK(A1,A2) @ concatK(B1,B2) (+add)(+bias)(+relu)
// BM=64, BN=128, BK=32, 128 threads, 8x8 micro-tile, packed f32x2 along N.
template <bool ADDEND, bool BIAS, bool RELU>
__global__ __launch_bounds__(128, 4)
void k_gemm(const float* __restrict__ A1, const float* __restrict__ A2, int lda,
            const float* __restrict__ B1, const float* __restrict__ B2,
            const float* __restrict__ add, const float* __restrict__ bias,
            float* __restrict__ C, int M, int N, int K, int kSplit) {
    const int BM = 64, BN = 128, BK = 32;
    const int AROW = 68;  // padded row (floats), keeps 16B alignment, spreads STS banks
    __shared__ float As[BK][AROW];   // [k][m]
    __shared__ float Bs[BK][BN];     // [k][n]

    int tid = threadIdx.x;
    int tn = tid & 15;   // 0..15 -> 8 cols each (128 cols)
    int tm = tid >> 4;   // 0..7  -> 8 rows each (64 rows)
    int m0 = blockIdx.y * BM;
    int n0 = blockIdx.x * BN;

    // A-loader coords: thread loads float4 along K, 4 rows per pass, 4 passes
    int a_m = tid >> 3;        // 0..15
    int a_k4 = (tid & 7) * 4;  // 0,4,...,28
    // B-loader coords: float4 along N, rows kk..kk+28 step 4
    int b_n4 = (tid & 31) * 4; // 0..124
    int b_k = tid >> 5;        // 0..3

    unsigned long long acc[8][4];
#pragma unroll
    for (int i = 0; i < 8; i++)
#pragma unroll
        for (int j = 0; j < 4; j++) acc[i][j] = 0ull;

    for (int k0 = 0; k0 < K; k0 += BK) {
        const float* Ap;
        const float* Bp;
        int ko;
        if (k0 < kSplit) { Ap = A1; Bp = B1; ko = k0; }
        else             { Ap = A2; Bp = B2; ko = k0 - kSplit; }

        // load A tile (64 x 32) transposed into As[k][m]
#pragma unroll
        for (int r = 0; r < 4; r++) {
            int m = a_m + r * 16;
            int gm = m0 + m;
            float4 v;
            if (gm < M) v = *(const float4*)(Ap + (long)gm * lda + ko + a_k4);
            else        v = make_float4(0.f, 0.f, 0.f, 0.f);
            As[a_k4 + 0][m] = v.x;
            As[a_k4 + 1][m] = v.y;
            As[a_k4 + 2][m] = v.z;
            As[a_k4 + 3][m] = v.w;
        }
        // load B tile (32 x 128)
#pragma unroll
        for (int r = 0; r < 8; r++) {
            int kk = b_k + r * 4;
            *(float4*)(&Bs[kk][b_n4]) = *(const float4*)(Bp + (long)(ko + kk) * N + n0 + b_n4);
        }
        __syncthreads();

#pragma unroll 8
        for (int k = 0; k < BK; k++) {
            float4 alo = *(const float4*)(&As[k][tm * 8]);
            float4 ahi = *(const float4*)(&As[k][tm * 8 + 4]);
            ulonglong2 bl = *(const ulonglong2*)(&Bs[k][tn * 8]);
            ulonglong2 bh = *(const ulonglong2*)(&Bs[k][tn * 8 + 4]);
            unsigned long long b2[4] = {bl.x, bl.y, bh.x, bh.y};
            unsigned long long ab[8];
            ab[0] = bcast2(alo.x); ab[1] = bcast2(alo.y);
            ab[2] = bcast2(alo.z); ab[3] = bcast2(alo.w);
            ab[4] = bcast2(ahi.x); ab[5] = bcast2(ahi.y);
            ab[6] = bcast2(ahi.z); ab[7] = bcast2(ahi.w);
#pragma unroll
            for (int i = 0; i < 8; i++)
#pragma unroll
                for (int j = 0; j < 4; j++)
                    acc[i][j] = ffma2(ab[i], b2[j], acc[i][j]);
        }
        __syncthreads();
    }

    // epilogue
    float bvals[8];
    if (BIAS) {
#pragma unroll
        for (int j = 0; j < 8; j++) bvals[j] = bias[n0 + tn * 8 + j];
    }
#pragma unroll
    for (int i = 0; i < 8; i++) {
        int m = m0 + tm * 8 + i;
        if (m >= M) continue;
        float v[8];
#pragma unroll
        for (int j = 0; j < 4; j++) unpack2(acc[i][j], v[2 * j], v[2 * j + 1]);
        long base = (long)m * N + n0 + tn * 8;
#pragma unroll
        for (int j = 0; j < 8; j++) {
            if (BIAS) v[j] += bvals[j];
            if (ADDEND) v[j] += add[base + j];
            if (RELU) v[j] = fmaxf(v[j], 0.f);
        }
        *(float4*)(C + base)     = make_float4(v[0], v[1], v[2], v[3]);
        *(float4*)(C + base + 4) = make_float4(v[4], v[5], v[6], v[7]);
    }
}

// ---------------- launch ----------------
extern "C" void kernel_launch(void* const* d_in, const int* in_sizes, int n_in,
                              void* d_out, int out_size) {
    const float* x   = (const float*)d_in[0];
    const float* ws1 = (const float*)d_in[1];
    const float* wn1 = (const float*)d_in[2];
    const float* b1  = (const float*)d_in[3];
    const float* ws2 = (const float*)d_in[4];
    const float* wn2 = (const float*)d_in[5];
    const float* b2  = (const float*)d_in[6];
    const int*   src = (const int*)d_in[7];
    const int*   dst = (const int*)d_in[8];
    float* out = (float*)d_out;

    float *agg, *h, *t;
    cudaGetSymbolAddress((void**)&agg, g_agg);
    cudaGetSymbolAddress((void**)&h, g_h);
    cudaGetSymbolAddress((void**)&t, g_t);

    // CSR build (per call; graph-capturable, no allocs)
    k_zero<<<(NN + 255) / 256, 256>>>();
    k_count<<<(NE + 255) / 256, 256>>>(dst);
    k_scan<<<1, 1024>>>();
    k_fill<<<(NE + 255) / 256, 256>>>(src, dst);

    int agg_blocks = (NN * 32 + 255) / 256;

    // layer 1: agg1 = mean_agg(x); h = relu([x|agg1] @ [ws1;wn1] + b1)  (concat-K dual GEMM)
    k_agg<<<agg_blocks, 256>>>(x, agg);
    {
        dim3 g((256 + 127) / 128, (NN + 63) / 64);
        k_gemm<false, true, true><<<g, 128>>>(x, agg, 128, ws1, wn1,
                                              nullptr, b1, h, NN, 256, 256, 128);
    }

    // layer 2 (reordered): t = h@wn2; agg2 = mean_agg(t); out = h@ws2 + agg2 + b2
    {
        dim3 g((128 + 127) / 128, (NN + 63) / 64);
        k_gemm<false, false, false><<<g, 128>>>(h, h, 256, wn2, wn2,
                                                nullptr, nullptr, t, NN, 128, 256, 256);
        k_agg<<<agg_blocks, 256>>>(t, agg);
        k_gemm<true, true, false><<<g, 128>>>(h, h, 256, ws2, ws2,
                                              agg, b2, out, NN, 128, 256, 256);
    }
}

// round 4
// speedup vs baseline: 1.1787x; 1.0306x over previous
#include <cuda_runtime.h>
#include <cuda_fp16.h>

#define NN 10000
#define NE 640000
// IN=128, HID=256, OUT=128

// ---------------- scratch (no allocations allowed) ----------------
__device__ int    g_cnt[NN];         // degree counts, then reused as fill cursor
__device__ int    g_row[NN + 1];     // CSR row offsets
__device__ int    g_col[NE];         // CSR column (src node per edge, grouped by dst)
__device__ float  g_agg[NN * 128];   // aggregation output (fp32, GEMM operand)
__device__ float  g_h[NN * 256];     // hidden activations (fp32)
__device__ __half g_xh[NN * 128];    // x converted to fp16 (gather source)
__device__ __half g_th[NN * 128];    // t = h @ w_neigh2 in fp16 (gather source)

// ---------------- f32x2 helpers ----------------
__device__ __forceinline__ unsigned long long bcast2(float a) {
    unsigned long long d;
    unsigned int u = __float_as_uint(a);
    asm("mov.b64 %0, {%1, %1};" : "=l"(d) : "r"(u));
    return d;
}
__device__ __forceinline__ unsigned long long ffma2(unsigned long long a,
                                                    unsigned long long b,
                                                    unsigned long long c) {
    unsigned long long d;
    asm("fma.rn.f32x2 %0, %1, %2, %3;" : "=l"(d) : "l"(a), "l"(b), "l"(c));
    return d;
}
__device__ __forceinline__ void unpack2(unsigned long long v, float& lo, float& hi) {
    unsigned int a, b;
    asm("mov.b64 {%0, %1}, %2;" : "=r"(a), "=r"(b) : "l"(v));
    lo = __uint_as_float(a);
    hi = __uint_as_float(b);
}
__device__ __forceinline__ unsigned int h2_bits(__half2 h) {
    unsigned int u;
    *(__half2*)&u = h;
    return u;
}

// ---------------- x -> fp16 conversion (vectorized) ----------------
__global__ void k_f2h(const float* __restrict__ in, __half* __restrict__ out, int n4) {
    int i = blockIdx.x * blockDim.x + threadIdx.x;
    if (i >= n4) return;
    float4 v = ((const float4*)in)[i];
    uint2 p;
    p.x = h2_bits(__floats2half2_rn(v.x, v.y));
    p.y = h2_bits(__floats2half2_rn(v.z, v.w));
    ((uint2*)out)[i] = p;
}

// ---------------- CSR build ----------------
__global__ void k_zero() {
    int i = blockIdx.x * blockDim.x + threadIdx.x;
    if (i < NN) g_cnt[i] = 0;
}

// ILP-4: 4 independent atomics per thread (latency hiding); NE % 4 == 0
__global__ void k_count(const int* __restrict__ dst) {
    int e4 = blockIdx.x * blockDim.x + threadIdx.x;
    if (e4 * 4 >= NE) return;
    int4 d = ((const int4*)dst)[e4];
    atomicAdd(&g_cnt[d.x], 1);
    atomicAdd(&g_cnt[d.y], 1);
    atomicAdd(&g_cnt[d.z], 1);
    atomicAdd(&g_cnt[d.w], 1);
}

// single-block exclusive scan over 10000 counts; also primes cursor (g_cnt)
__global__ void k_scan() {
    __shared__ int part[1024];
    const int CH = 10;  // 1024*10 >= 10000
    int t = threadIdx.x;
    int base = t * CH;
    int loc[CH];
    int s = 0;
#pragma unroll
    for (int i = 0; i < CH; i++) {
        int idx = base + i;
        int v = (idx < NN) ? g_cnt[idx] : 0;
        loc[i] = s;
        s += v;
    }
    part[t] = s;
    __syncthreads();
    for (int off = 1; off < 1024; off <<= 1) {
        int v = (t >= off) ? part[t - off] : 0;
        __syncthreads();
        part[t] += v;
        __syncthreads();
    }
    int offs = (t > 0) ? part[t - 1] : 0;
#pragma unroll
    for (int i = 0; i < CH; i++) {
        int idx = base + i;
        if (idx < NN) {
            int r = offs + loc[i];
            g_row[idx] = r;
            g_cnt[idx] = r;  // cursor for fill
        }
    }
    if (t == 0) g_row[NN] = NE;
}

// ILP-4 fill
__global__ void k_fill(const int* __restrict__ src, const int* __restrict__ dst) {
    int e4 = blockIdx.x * blockDim.x + threadIdx.x;
    if (e4 * 4 >= NE) return;
    int4 d = ((const int4*)dst)[e4];
    int4 s = ((const int4*)src)[e4];
    int p0 = atomicAdd(&g_cnt[d.x], 1);
    int p1 = atomicAdd(&g_cnt[d.y], 1);
    int p2 = atomicAdd(&g_cnt[d.z], 1);
    int p3 = atomicAdd(&g_cnt[d.w], 1);
    g_col[p0] = s.x;
    g_col[p1] = s.y;
    g_col[p2] = s.z;
    g_col[p3] = s.w;
}

// ---------------- mean aggregation (fp16 source, fp32 accumulate) ----------------
// warp per node; 128 halfs = 32 lanes x uint2 (4 halfs per lane)
__global__ void k_agg_h(const __half* __restrict__ feat, float* __restrict__ out) {
    int warp = (blockIdx.x * blockDim.x + threadIdx.x) >> 5;
    int lane = threadIdx.x & 31;
    if (warp >= NN) return;
    int beg = g_row[warp];
    int end = g_row[warp + 1];
    const uint2* f = (const uint2*)feat;

    float4 a0 = make_float4(0.f, 0.f, 0.f, 0.f);
    float4 a1 = a0, a2 = a0, a3 = a0;

    int e = beg;
    for (; e + 4 <= end; e += 4) {
        int s0 = g_col[e + 0];
        int s1 = g_col[e + 1];
        int s2 = g_col[e + 2];
        int s3 = g_col[e + 3];
        uint2 v0 = __ldg(&f[s0 * 32 + lane]);
        uint2 v1 = __ldg(&f[s1 * 32 + lane]);
        uint2 v2 = __ldg(&f[s2 * 32 + lane]);
        uint2 v3 = __ldg(&f[s3 * 32 + lane]);
        float2 p, q;
        p = __half22float2(*(__half2*)&v0.x); q = __half22float2(*(__half2*)&v0.y);
        a0.x += p.x; a0.y += p.y; a0.z += q.x; a0.w += q.y;
        p = __half22float2(*(__half2*)&v1.x); q = __half22float2(*(__half2*)&v1.y);
        a1.x += p.x; a1.y += p.y; a1.z += q.x; a1.w += q.y;
        p = __half22float2(*(__half2*)&v2.x); q = __half22float2(*(__half2*)&v2.y);
        a2.x += p.x; a2.y += p.y; a2.z += q.x; a2.w += q.y;
        p = __half22float2(*(__half2*)&v3.x); q = __half22float2(*(__half2*)&v3.y);
        a3.x += p.x; a3.y += p.y; a3.z += q.x; a3.w += q.y;
    }
    for (; e < end; e++) {
        int s = g_col[e];
        uint2 v = __ldg(&f[s * 32 + lane]);
        float2 p = __half22float2(*(__half2*)&v.x);
        float2 q = __half22float2(*(__half2*)&v.y);
        a0.x += p.x; a0.y += p.y; a0.z += q.x; a0.w += q.y;
    }
    a0.x += a1.x + a2.x + a3.x;
    a0.y += a1.y + a2.y + a3.y;
    a0.z += a1.z + a2.z + a3.z;
    a0.w += a1.w + a2.w + a3.w;

    float inv = 1.0f / fmaxf((float)(end - beg), 1.0f);
    a0.x *= inv; a0.y *= inv; a0.z *= inv; a0.w *= inv;
    ((float4*)out)[warp * 32 + lane] = a0;
}

// ---------------- f32x2 SGEMM: C = concatK(A1,A2) @ concatK(B1,B2) (+add)(+bias)(+relu)
// BM=64, BN=128, BK=32, 128 threads, 8x8 micro-tile, packed f32x2 along N.
// HALFOUT: write fp16 instead of fp32 (for the pre-aggregation tensor t)
template <bool ADDEND, bool BIAS, bool RELU, bool HALFOUT>
__global__ __launch_bounds__(128, 4)
void k_gemm(const float* __restrict__ A1, const float* __restrict__ A2, int lda,
            const float* __restrict__ B1, const float* __restrict__ B2,
            const float* __restrict__ add, const float* __restrict__ bias,
            void* __restrict__ Cv, int M, int N, int K, int kSplit) {
    const int BM = 64, BN = 128, BK = 32;
    const int AROW = 68;
    __shared__ float As[BK][AROW];   // [k][m]
    __shared__ float Bs[BK][BN];     // [k][n]

    int tid = threadIdx.x;
    int tn = tid & 15;   // 0..15 -> 8 cols each (128 cols)
    int tm = tid >> 4;   // 0..7  -> 8 rows each (64 rows)
    int m0 = blockIdx.y * BM;
    int n0 = blockIdx.x * BN;

    int a_m = tid >> 3;        // 0..15
    int a_k4 = (tid & 7) * 4;  // 0,4,...,28
    int b_n4 = (tid & 31) * 4; // 0..124
    int b_k = tid >> 5;        // 0..3

    unsigned long long acc[8][4];
#pragma unroll
    for (int i = 0; i < 8; i++)
#pragma unroll
        for (int j = 0; j < 4; j++) acc[i][j] = 0ull;

    for (int k0 = 0; k0 < K; k0 += BK) {
        const float* Ap;
        const float* Bp;
        int ko;
        if (k0 < kSplit) { Ap = A1; Bp = B1; ko = k0; }
        else             { Ap = A2; Bp = B2; ko = k0 - kSplit; }

#pragma unroll
        for (int r = 0; r < 4; r++) {
            int m = a_m + r * 16;
            int gm = m0 + m;
            float4 v;
            if (gm < M) v = *(const float4*)(Ap + (long)gm * lda + ko + a_k4);
            else        v = make_float4(0.f, 0.f, 0.f, 0.f);
            As[a_k4 + 0][m] = v.x;
            As[a_k4 + 1][m] = v.y;
            As[a_k4 + 2][m] = v.z;
            As[a_k4 + 3][m] = v.w;
        }
#pragma unroll
        for (int r = 0; r < 8; r++) {
            int kk = b_k + r * 4;
            *(float4*)(&Bs[kk][b_n4]) = *(const float4*)(Bp + (long)(ko + kk) * N + n0 + b_n4);
        }
        __syncthreads();

#pragma unroll 8
        for (int k = 0; k < BK; k++) {
            float4 alo = *(const float4*)(&As[k][tm * 8]);
            float4 ahi = *(const float4*)(&As[k][tm * 8 + 4]);
            ulonglong2 bl = *(const ulonglong2*)(&Bs[k][tn * 8]);
            ulonglong2 bh = *(const ulonglong2*)(&Bs[k][tn * 8 + 4]);
            unsigned long long b2[4] = {bl.x, bl.y, bh.x, bh.y};
            unsigned long long ab[8];
            ab[0] = bcast2(alo.x); ab[1] = bcast2(alo.y);
            ab[2] = bcast2(alo.z); ab[3] = bcast2(alo.w);
            ab[4] = bcast2(ahi.x); ab[5] = bcast2(ahi.y);
            ab[6] = bcast2(ahi.z); ab[7] = bcast2(ahi.w);
#pragma unroll
            for (int i = 0; i < 8; i++)
#pragma unroll
                for (int j = 0; j < 4; j++)
                    acc[i][j] = ffma2(ab[i], b2[j], acc[i][j]);
        }
        __syncthreads();
    }

    float bvals[8];
    if (BIAS) {
#pragma unroll
        for (int j = 0; j < 8; j++) bvals[j] = bias[n0 + tn * 8 + j];
    }
#pragma unroll
    for (int i = 0; i < 8; i++) {
        int m = m0 + tm * 8 + i;
        if (m >= M) continue;
        float v[8];
#pragma unroll
        for (int j = 0; j < 4; j++) unpack2(acc[i][j], v[2 * j], v[2 * j + 1]);
        long base = (long)m * N + n0 + tn * 8;
#pragma unroll
        for (int j = 0; j < 8; j++) {
            if (BIAS) v[j] += bvals[j];
            if (ADDEND) v[j] += add[base + j];
            if (RELU) v[j] = fmaxf(v[j], 0.f);
        }
        if (HALFOUT) {
            uint4 p;
            p.x = h2_bits(__floats2half2_rn(v[0], v[1]));
            p.y = h2_bits(__floats2half2_rn(v[2], v[3]));
            p.z = h2_bits(__floats2half2_rn(v[4], v[5]));
            p.w = h2_bits(__floats2half2_rn(v[6], v[7]));
            *(uint4*)((__half*)Cv + base) = p;
        } else {
            float* C = (float*)Cv;
            *(float4*)(C + base)     = make_float4(v[0], v[1], v[2], v[3]);
            *(float4*)(C + base + 4) = make_float4(v[4], v[5], v[6], v[7]);
        }
    }
}

// ---------------- launch ----------------
extern "C" void kernel_launch(void* const* d_in, const int* in_sizes, int n_in,
                              void* d_out, int out_size) {
    const float* x   = (const float*)d_in[0];
    const float* ws1 = (const float*)d_in[1];
    const float* wn1 = (const float*)d_in[2];
    const float* b1  = (const float*)d_in[3];
    const float* ws2 = (const float*)d_in[4];
    const float* wn2 = (const float*)d_in[5];
    const float* b2  = (const float*)d_in[6];
    const int*   src = (const int*)d_in[7];
    const int*   dst = (const int*)d_in[8];
    float* out = (float*)d_out;

    float *agg, *h;
    __half *xh, *th;
    cudaGetSymbolAddress((void**)&agg, g_agg);
    cudaGetSymbolAddress((void**)&h, g_h);
    cudaGetSymbolAddress((void**)&xh, g_xh);
    cudaGetSymbolAddress((void**)&th, g_th);

    // x -> fp16 (gather source), independent of CSR
    k_f2h<<<(NN * 128 / 4 + 255) / 256, 256>>>(x, xh, NN * 128 / 4);

    // CSR build
    k_zero<<<(NN + 255) / 256, 256>>>();
    k_count<<<(NE / 4 + 255) / 256, 256>>>(dst);
    k_scan<<<1, 1024>>>();
    k_fill<<<(NE / 4 + 255) / 256, 256>>>(src, dst);

    int agg_blocks = (NN * 32 + 255) / 256;

    // layer 1: agg1 = mean_agg(x); h = relu([x|agg1] @ [ws1;wn1] + b1)
    k_agg_h<<<agg_blocks, 256>>>(xh, agg);
    {
        dim3 g(256 / 128, (NN + 63) / 64);
        k_gemm<false, true, true, false><<<g, 128>>>(x, agg, 128, ws1, wn1,
                                                     nullptr, b1, h, NN, 256, 256, 128);
    }

    // layer 2 (reordered): t = h@wn2 (fp16); agg2 = mean_agg(t); out = h@ws2 + agg2 + b2
    {
        dim3 g(128 / 128, (NN + 63) / 64);
        k_gemm<false, false, false, true><<<g, 128>>>(h, h, 256, wn2, wn2,
                                                      nullptr, nullptr, th, NN, 128, 256, 256);
        k_agg_h<<<agg_blocks, 256>>>(th, agg);
        k_gemm<true, true, false, false><<<g, 128>>>(h, h, 256, ws2, ws2,
                                                     agg, b2, out, NN, 128, 256, 256);
    }
}

// round 5
// speedup vs baseline: 1.1967x; 1.0153x over previous
#include <cuda_runtime.h>
#include <cuda_fp16.h>

#define NN 10000
#define NE 640000
#define NN_PAD 10240
// IN=128, HID=256, OUT=128

// ---------------- scratch (no allocations allowed) ----------------
__device__ int4   g_cnt4[NN_PAD / 4];  // degree counts (padded), then fill cursor
#define g_cnt ((int*)g_cnt4)
__device__ int    g_row[NN + 1];     // CSR row offsets
__device__ int    g_col[NE];         // CSR column (src node per edge, grouped by dst)
__device__ float  g_agg[NN * 128];   // aggregation output (fp32, GEMM operand)
__device__ float  g_h[NN * 256];     // hidden activations (fp32)
__device__ __half g_xh[NN * 128];    // x converted to fp16 (gather source)
__device__ __half g_th[NN * 128];    // t = h @ w_neigh2 in fp16 (gather source)

// ---------------- f32x2 helpers ----------------
__device__ __forceinline__ unsigned long long bcast2(float a) {
    unsigned long long d;
    unsigned int u = __float_as_uint(a);
    asm("mov.b64 %0, {%1, %1};" : "=l"(d) : "r"(u));
    return d;
}
__device__ __forceinline__ unsigned long long ffma2(unsigned long long a,
                                                    unsigned long long b,
                                                    unsigned long long c) {
    unsigned long long d;
    asm("fma.rn.f32x2 %0, %1, %2, %3;" : "=l"(d) : "l"(a), "l"(b), "l"(c));
    return d;
}
__device__ __forceinline__ void unpack2(unsigned long long v, float& lo, float& hi) {
    unsigned int a, b;
    asm("mov.b64 {%0, %1}, %2;" : "=r"(a), "=r"(b) : "l"(v));
    lo = __uint_as_float(a);
    hi = __uint_as_float(b);
}
__device__ __forceinline__ unsigned int h2_bits(__half2 h) {
    unsigned int u;
    *(__half2*)&u = h;
    return u;
}

// ---------------- init: x -> fp16 AND zero g_cnt (fused) ----------------
__global__ void k_init(const float* __restrict__ in, __half* __restrict__ out, int n4) {
    int i = blockIdx.x * blockDim.x + threadIdx.x;
    if (i < NN_PAD / 4) g_cnt4[i] = make_int4(0, 0, 0, 0);
    if (i >= n4) return;
    float4 v = ((const float4*)in)[i];
    uint2 p;
    p.x = h2_bits(__floats2half2_rn(v.x, v.y));
    p.y = h2_bits(__floats2half2_rn(v.z, v.w));
    ((uint2*)out)[i] = p;
}

// ---------------- CSR build ----------------
// ILP-4: 4 independent atomics per thread (latency hiding); NE % 4 == 0
__global__ void k_count(const int* __restrict__ dst) {
    int e4 = blockIdx.x * blockDim.x + threadIdx.x;
    if (e4 * 4 >= NE) return;
    int4 d = ((const int4*)dst)[e4];
    atomicAdd(&g_cnt[d.x], 1);
    atomicAdd(&g_cnt[d.y], 1);
    atomicAdd(&g_cnt[d.z], 1);
    atomicAdd(&g_cnt[d.w], 1);
}

// single-block scan: 256 threads x 40 elements, warp-shuffle based (2 barriers)
__global__ void k_scan() {
    const int CH = 40;  // 256*40 = 10240 = NN_PAD
    __shared__ int wsum[8];
    int t = threadIdx.x;
    int lane = t & 31;
    int wid = t >> 5;

    int v[CH];
#pragma unroll
    for (int i = 0; i < 10; i++) {
        int4 w = g_cnt4[t * 10 + i];
        v[i * 4 + 0] = w.x; v[i * 4 + 1] = w.y;
        v[i * 4 + 2] = w.z; v[i * 4 + 3] = w.w;
    }
    int pre[CH];
    int s = 0;
#pragma unroll
    for (int i = 0; i < CH; i++) { pre[i] = s; s += v[i]; }

    // inclusive warp scan of s
    int inc = s;
#pragma unroll
    for (int off = 1; off < 32; off <<= 1) {
        int n = __shfl_up_sync(0xffffffffu, inc, off);
        if (lane >= off) inc += n;
    }
    if (lane == 31) wsum[wid] = inc;
    __syncthreads();
    if (t < 8) {
        int w = wsum[t];
#pragma unroll
        for (int off = 1; off < 8; off <<= 1) {
            int n = __shfl_up_sync(0xffu, w, off, 8);
            if (t >= off) w += n;
        }
        wsum[t] = w;  // inclusive warp sums
    }
    __syncthreads();

    int offset = ((wid > 0) ? wsum[wid - 1] : 0) + (inc - s);  // exclusive prefix
    int base = t * CH;
#pragma unroll
    for (int i = 0; i < CH; i++) {
        int idx = base + i;
        if (idx < NN) {
            int r = offset + pre[i];
            g_row[idx] = r;
            g_cnt[idx] = r;  // cursor for fill
        }
    }
    if (t == 0) g_row[NN] = NE;
}

// ILP-4 fill
__global__ void k_fill(const int* __restrict__ src, const int* __restrict__ dst) {
    int e4 = blockIdx.x * blockDim.x + threadIdx.x;
    if (e4 * 4 >= NE) return;
    int4 d = ((const int4*)dst)[e4];
    int4 s = ((const int4*)src)[e4];
    int p0 = atomicAdd(&g_cnt[d.x], 1);
    int p1 = atomicAdd(&g_cnt[d.y], 1);
    int p2 = atomicAdd(&g_cnt[d.z], 1);
    int p3 = atomicAdd(&g_cnt[d.w], 1);
    g_col[p0] = s.x;
    g_col[p1] = s.y;
    g_col[p2] = s.z;
    g_col[p3] = s.w;
}

// ---------------- mean aggregation (fp16 source, fp32 accumulate) ----------------
__global__ void k_agg_h(const __half* __restrict__ feat, float* __restrict__ out) {
    int warp = (blockIdx.x * blockDim.x + threadIdx.x) >> 5;
    int lane = threadIdx.x & 31;
    if (warp >= NN) return;
    int beg = g_row[warp];
    int end = g_row[warp + 1];
    const uint2* f = (const uint2*)feat;

    float4 a0 = make_float4(0.f, 0.f, 0.f, 0.f);
    float4 a1 = a0, a2 = a0, a3 = a0;

    int e = beg;
    for (; e + 4 <= end; e += 4) {
        int s0 = g_col[e + 0];
        int s1 = g_col[e + 1];
        int s2 = g_col[e + 2];
        int s3 = g_col[e + 3];
        uint2 v0 = __ldg(&f[s0 * 32 + lane]);
        uint2 v1 = __ldg(&f[s1 * 32 + lane]);
        uint2 v2 = __ldg(&f[s2 * 32 + lane]);
        uint2 v3 = __ldg(&f[s3 * 32 + lane]);
        float2 p, q;
        p = __half22float2(*(__half2*)&v0.x); q = __half22float2(*(__half2*)&v0.y);
        a0.x += p.x; a0.y += p.y; a0.z += q.x; a0.w += q.y;
        p = __half22float2(*(__half2*)&v1.x); q = __half22float2(*(__half2*)&v1.y);
        a1.x += p.x; a1.y += p.y; a1.z += q.x; a1.w += q.y;
        p = __half22float2(*(__half2*)&v2.x); q = __half22float2(*(__half2*)&v2.y);
        a2.x += p.x; a2.y += p.y; a2.z += q.x; a2.w += q.y;
        p = __half22float2(*(__half2*)&v3.x); q = __half22float2(*(__half2*)&v3.y);
        a3.x += p.x; a3.y += p.y; a3.z += q.x; a3.w += q.y;
    }
    for (; e < end; e++) {
        int s = g_col[e];
        uint2 v = __ldg(&f[s * 32 + lane]);
        float2 p = __half22float2(*(__half2*)&v.x);
        float2 q = __half22float2(*(__half2*)&v.y);
        a0.x += p.x; a0.y += p.y; a0.z += q.x; a0.w += q.y;
    }
    a0.x += a1.x + a2.x + a3.x;
    a0.y += a1.y + a2.y + a3.y;
    a0.z += a1.z + a2.z + a3.z;
    a0.w += a1.w + a2.w + a3.w;

    float inv = 1.0f / fmaxf((float)(end - beg), 1.0f);
    a0.x *= inv; a0.y *= inv; a0.z *= inv; a0.w *= inv;
    ((float4*)out)[warp * 32 + lane] = a0;
}

// ---------------- f32x2 SGEMM with register-prefetch pipeline ----------------
// BM=64, BN=128, BK=32, 128 threads, 8x8 micro-tile, packed f32x2 along N.
template <bool ADDEND, bool BIAS, bool RELU, bool HALFOUT>
__global__ __launch_bounds__(128, 3)
void k_gemm(const float* __restrict__ A1, const float* __restrict__ A2, int lda,
            const float* __restrict__ B1, const float* __restrict__ B2,
            const float* __restrict__ add, const float* __restrict__ bias,
            void* __restrict__ Cv, int M, int N, int K, int kSplit) {
    const int BM = 64, BN = 128, BK = 32;
    const int AROW = 68;
    __shared__ float As[BK][AROW];   // [k][m]
    __shared__ float Bs[BK][BN];     // [k][n]

    int tid = threadIdx.x;
    int tn = tid & 15;   // 0..15 -> 8 cols each
    int tm = tid >> 4;   // 0..7  -> 8 rows each
    int m0 = blockIdx.y * BM;
    int n0 = blockIdx.x * BN;

    int a_m = tid >> 3;        // 0..15
    int a_k4 = (tid & 7) * 4;  // 0,4,...,28
    int b_n4 = (tid & 31) * 4; // 0..124
    int b_k = tid >> 5;        // 0..3

    unsigned long long acc[8][4];
#pragma unroll
    for (int i = 0; i < 8; i++)
#pragma unroll
        for (int j = 0; j < 4; j++) acc[i][j] = 0ull;

    float4 ra[4];
    float4 rb[8];

    auto loadRegs = [&](int k0) {
        const float* Ap;
        const float* Bp;
        int ko;
        if (k0 < kSplit) { Ap = A1; Bp = B1; ko = k0; }
        else             { Ap = A2; Bp = B2; ko = k0 - kSplit; }
#pragma unroll
        for (int r = 0; r < 4; r++) {
            int gm = m0 + a_m + r * 16;
            ra[r] = (gm < M) ? *(const float4*)(Ap + (long)gm * lda + ko + a_k4)
                             : make_float4(0.f, 0.f, 0.f, 0.f);
        }
#pragma unroll
        for (int r = 0; r < 8; r++) {
            int kk = b_k + r * 4;
            rb[r] = *(const float4*)(Bp + (long)(ko + kk) * N + n0 + b_n4);
        }
    };

    loadRegs(0);
    int T = K / BK;
    for (int it = 0; it < T; it++) {
        // stage regs -> smem
#pragma unroll
        for (int r = 0; r < 4; r++) {
            int m = a_m + r * 16;
            As[a_k4 + 0][m] = ra[r].x;
            As[a_k4 + 1][m] = ra[r].y;
            As[a_k4 + 2][m] = ra[r].z;
            As[a_k4 + 3][m] = ra[r].w;
        }
#pragma unroll
        for (int r = 0; r < 8; r++) {
            int kk = b_k + r * 4;
            *(float4*)(&Bs[kk][b_n4]) = rb[r];
        }
        __syncthreads();

        // prefetch next tile into regs (overlaps with compute below)
        if (it + 1 < T) loadRegs((it + 1) * BK);

#pragma unroll 8
        for (int k = 0; k < BK; k++) {
            float4 alo = *(const float4*)(&As[k][tm * 8]);
            float4 ahi = *(const float4*)(&As[k][tm * 8 + 4]);
            ulonglong2 bl = *(const ulonglong2*)(&Bs[k][tn * 8]);
            ulonglong2 bh = *(const ulonglong2*)(&Bs[k][tn * 8 + 4]);
            unsigned long long b2[4] = {bl.x, bl.y, bh.x, bh.y};
            unsigned long long ab[8];
            ab[0] = bcast2(alo.x); ab[1] = bcast2(alo.y);
            ab[2] = bcast2(alo.z); ab[3] = bcast2(alo.w);
            ab[4] = bcast2(ahi.x); ab[5] = bcast2(ahi.y);
            ab[6] = bcast2(ahi.z); ab[7] = bcast2(ahi.w);
#pragma unroll
            for (int i = 0; i < 8; i++)
#pragma unroll
                for (int j = 0; j < 4; j++)
                    acc[i][j] = ffma2(ab[i], b2[j], acc[i][j]);
        }
        __syncthreads();
    }

    float bvals[8];
    if (BIAS) {
#pragma unroll
        for (int j = 0; j < 8; j++) bvals[j] = bias[n0 + tn * 8 + j];
    }
#pragma unroll
    for (int i = 0; i < 8; i++) {
        int m = m0 + tm * 8 + i;
        if (m >= M) continue;
        float v[8];
#pragma unroll
        for (int j = 0; j < 4; j++) unpack2(acc[i][j], v[2 * j], v[2 * j + 1]);
        long base = (long)m * N + n0 + tn * 8;
#pragma unroll
        for (int j = 0; j < 8; j++) {
            if (BIAS) v[j] += bvals[j];
            if (ADDEND) v[j] += add[base + j];
            if (RELU) v[j] = fmaxf(v[j], 0.f);
        }
        if (HALFOUT) {
            uint4 p;
            p.x = h2_bits(__floats2half2_rn(v[0], v[1]));
            p.y = h2_bits(__floats2half2_rn(v[2], v[3]));
            p.z = h2_bits(__floats2half2_rn(v[4], v[5]));
            p.w = h2_bits(__floats2half2_rn(v[6], v[7]));
            *(uint4*)((__half*)Cv + base) = p;
        } else {
            float* C = (float*)Cv;
            *(float4*)(C + base)     = make_float4(v[0], v[1], v[2], v[3]);
            *(float4*)(C + base + 4) = make_float4(v[4], v[5], v[6], v[7]);
        }
    }
}

// ---------------- launch ----------------
extern "C" void kernel_launch(void* const* d_in, const int* in_sizes, int n_in,
                              void* d_out, int out_size) {
    const float* x   = (const float*)d_in[0];
    const float* ws1 = (const float*)d_in[1];
    const float* wn1 = (const float*)d_in[2];
    const float* b1  = (const float*)d_in[3];
    const float* ws2 = (const float*)d_in[4];
    const float* wn2 = (const float*)d_in[5];
    const float* b2  = (const float*)d_in[6];
    const int*   src = (const int*)d_in[7];
    const int*   dst = (const int*)d_in[8];
    float* out = (float*)d_out;

    float *agg, *h;
    __half *xh, *th;
    cudaGetSymbolAddress((void**)&agg, g_agg);
    cudaGetSymbolAddress((void**)&h, g_h);
    cudaGetSymbolAddress((void**)&xh, g_xh);
    cudaGetSymbolAddress((void**)&th, g_th);

    // fused: x -> fp16 + zero counters
    k_init<<<(NN * 128 / 4 + 255) / 256, 256>>>(x, xh, NN * 128 / 4);

    // CSR build
    k_count<<<(NE / 4 + 255) / 256, 256>>>(dst);
    k_scan<<<1, 256>>>();
    k_fill<<<(NE / 4 + 255) / 256, 256>>>(src, dst);

    int agg_blocks = (NN * 32 + 255) / 256;

    // layer 1: agg1 = mean_agg(x); h = relu([x|agg1] @ [ws1;wn1] + b1)
    k_agg_h<<<agg_blocks, 256>>>(xh, agg);
    {
        dim3 g(256 / 128, (NN + 63) / 64);
        k_gemm<false, true, true, false><<<g, 128>>>(x, agg, 128, ws1, wn1,
                                                     nullptr, b1, h, NN, 256, 256, 128);
    }

    // layer 2 (reordered): t = h@wn2 (fp16); agg2 = mean_agg(t); out = h@ws2 + agg2 + b2
    {
        dim3 g(128 / 128, (NN + 63) / 64);
        k_gemm<false, false, false, true><<<g, 128>>>(h, h, 256, wn2, wn2,
                                                      nullptr, nullptr, th, NN, 128, 256, 256);
        k_agg_h<<<agg_blocks, 256>>>(th, agg);
        k_gemm<true, true, false, false><<<g, 128>>>(h, h, 256, ws2, ws2,
                                                     agg, b2, out, NN, 128, 256, 256);
    }
}